// round 2
// baseline (speedup 1.0000x reference)
#include <cuda_runtime.h>
#include <cstdint>

// Problem constants
#define B_   4
#define S_   2048
#define E_   1024
#define H_   16
#define D_   64
#define QD_  1024
#define KD_  768
#define VD_  768
#define M_   (B_ * S_)          // 8192 flattened tokens
#define BH_  (B_ * H_)          // 64

// ---------------- device scratch (no allocations allowed) ----------------
__device__ float g_q[M_ * E_];
__device__ float g_k[M_ * E_];
__device__ float g_v[M_ * E_];
__device__ float g_ctx[M_ * E_];
__device__ float g_rmax[BH_ * S_];
__device__ float g_rinv[BH_ * S_];

// ---------------- fast exp via FFMA (avoids MUFU bottleneck) -------------
__device__ __forceinline__ float fast_exp(float x) {
    float t = x * 1.44269504088896341f;      // x * log2(e)
    t = fmaxf(t, -125.0f);                   // clamp (softmax arg <= 0 anyway)
    float r = t + 12582912.0f;               // round-to-nearest via magic number
    int   n = __float_as_int(r) - 0x4B400000;
    float f = t - (r - 12582912.0f);         // f in [-0.5, 0.5]
    float p = 1.33336498e-3f;
    p = fmaf(p, f, 9.61011466e-3f);
    p = fmaf(p, f, 5.55036595e-2f);
    p = fmaf(p, f, 2.40226510e-1f);
    p = fmaf(p, f, 6.93147182e-1f);
    p = fmaf(p, f, 1.0f);
    return __int_as_float((n + 127) << 23) * p;
}

// ---------------- generic GEMM with bias: C[M,N] = A[M,K]@W[K,N] + b -----
// BM=BN=64, BK=16, 256 threads, 4x4 per thread. M%64==0, N%64==0, K%16==0.
#define GBM 64
#define GBN 64
#define GBK 16
__global__ __launch_bounds__(256) void gemm_bias_kernel(
    const float* __restrict__ A, const float* __restrict__ W,
    const float* __restrict__ bias, float* __restrict__ C,
    int M, int N, int K)
{
    __shared__ float As[GBK][GBM + 1];   // transposed A tile
    __shared__ float Ws[GBK][GBN];
    const int t  = threadIdx.x;
    const int tx = t & 15;
    const int ty = t >> 4;
    const int m0 = blockIdx.y * GBM;
    const int n0 = blockIdx.x * GBN;

    float acc[4][4] = {};
    for (int k0 = 0; k0 < K; k0 += GBK) {
        #pragma unroll
        for (int l = 0; l < 4; l++) {
            int idx = t + l * 256;
            int r = idx >> 4, c = idx & 15;            // r<64, c<16
            As[c][r] = A[(size_t)(m0 + r) * K + k0 + c];
        }
        #pragma unroll
        for (int l = 0; l < 4; l++) {
            int idx = t + l * 256;
            int r = idx >> 6, c = idx & 63;            // r<16, c<64
            Ws[r][c] = W[(size_t)(k0 + r) * N + n0 + c];
        }
        __syncthreads();
        #pragma unroll
        for (int kk = 0; kk < GBK; kk++) {
            float a[4], b[4];
            #pragma unroll
            for (int i = 0; i < 4; i++) a[i] = As[kk][ty * 4 + i];
            #pragma unroll
            for (int j = 0; j < 4; j++) b[j] = Ws[kk][tx * 4 + j];
            #pragma unroll
            for (int i = 0; i < 4; i++)
                #pragma unroll
                for (int j = 0; j < 4; j++)
                    acc[i][j] = fmaf(a[i], b[j], acc[i][j]);
        }
        __syncthreads();
    }
    #pragma unroll
    for (int i = 0; i < 4; i++) {
        int row = m0 + ty * 4 + i;
        #pragma unroll
        for (int j = 0; j < 4; j++) {
            int col = n0 + tx * 4 + j;
            C[(size_t)row * N + col] = acc[i][j] + bias[col];
        }
    }
}

// ---------------- scores: raw = (Qh @ Kh^T) * 0.125 ----------------------
// grid (S/64, S/64, BH), block 256, 4x4 per thread, full K(=D=64) in smem
__global__ __launch_bounds__(256) void scores_kernel(
    const float* __restrict__ q, const float* __restrict__ k,
    float* __restrict__ Wbuf)
{
    __shared__ float Qs[64][65];
    __shared__ float Ks[64][65];
    const int bh = blockIdx.z;
    const int b  = bh >> 4, h = bh & 15;
    const int i0 = blockIdx.y * 64;
    const int j0 = blockIdx.x * 64;
    const int t  = threadIdx.x;
    const int tx = t & 15, ty = t >> 4;

    const float* qb = q + (size_t)b * S_ * E_ + h * D_;
    const float* kb = k + (size_t)b * S_ * E_ + h * D_;
    #pragma unroll
    for (int l = 0; l < 16; l++) {
        int idx = t + l * 256;
        int r = idx >> 6, c = idx & 63;
        Qs[r][c] = qb[(size_t)(i0 + r) * E_ + c];
        Ks[r][c] = kb[(size_t)(j0 + r) * E_ + c];
    }
    __syncthreads();

    float acc[4][4] = {};
    #pragma unroll 8
    for (int d = 0; d < 64; d++) {
        float a[4], bb[4];
        #pragma unroll
        for (int i = 0; i < 4; i++) a[i]  = Qs[ty * 4 + i][d];
        #pragma unroll
        for (int j = 0; j < 4; j++) bb[j] = Ks[tx * 4 + j][d];
        #pragma unroll
        for (int i = 0; i < 4; i++)
            #pragma unroll
            for (int j = 0; j < 4; j++)
                acc[i][j] = fmaf(a[i], bb[j], acc[i][j]);
    }
    float* out = Wbuf + ((size_t)bh * S_ + i0) * S_ + j0;
    #pragma unroll
    for (int i = 0; i < 4; i++)
        #pragma unroll
        for (int j = 0; j < 4; j++)
            out[(size_t)(ty * 4 + i) * S_ + tx * 4 + j] = acc[i][j] * 0.125f;
}

// ---------------- per-row max & 1/sum(exp) -------------------------------
// one block per row (BH*S rows), 256 threads, 8 elems each kept in regs
__global__ __launch_bounds__(256) void stats_kernel(
    const float* __restrict__ Wbuf,
    float* __restrict__ rmax, float* __restrict__ rinv)
{
    const size_t row = blockIdx.x;
    const float* p = Wbuf + row * S_;
    const int t = threadIdx.x;
    __shared__ float red[8];

    float v[8];
    float m = -1e30f;
    #pragma unroll
    for (int i = 0; i < 8; i++) { v[i] = p[t + i * 256]; m = fmaxf(m, v[i]); }
    #pragma unroll
    for (int o = 16; o; o >>= 1) m = fmaxf(m, __shfl_xor_sync(0xFFFFFFFFu, m, o));
    if ((t & 31) == 0) red[t >> 5] = m;
    __syncthreads();
    float m8 = red[t & 7];
    #pragma unroll
    for (int o = 4; o; o >>= 1) m8 = fmaxf(m8, __shfl_xor_sync(0xFFFFFFFFu, m8, o));
    m = m8;   // now identical in every thread
    __syncthreads();

    float s = 0.0f;
    #pragma unroll
    for (int i = 0; i < 8; i++) s += fast_exp(v[i] - m);
    #pragma unroll
    for (int o = 16; o; o >>= 1) s += __shfl_xor_sync(0xFFFFFFFFu, s, o);
    if ((t & 31) == 0) red[t >> 5] = s;
    __syncthreads();
    if (t == 0) {
        float tot = 0.0f;
        #pragma unroll
        for (int i = 0; i < 8; i++) tot += red[i];
        rmax[row] = m;
        rinv[row] = 1.0f / tot;
    }
}

// ---------------- normalize weights in-place + AV ------------------------
// grid (S/64, BH). Block covers 64 q-rows x all D=64 dims; loops over k.
__global__ __launch_bounds__(256) void av_kernel(
    float* __restrict__ Wbuf, const float* __restrict__ v,
    float* __restrict__ ctx,
    const float* __restrict__ rmax, const float* __restrict__ rinv)
{
    __shared__ float Ps[64][65];
    __shared__ float Vs[64][65];
    __shared__ float smax[64], sinv[64];
    const int bh = blockIdx.y;
    const int b  = bh >> 4, h = bh & 15;
    const int i0 = blockIdx.x * 64;
    const int t  = threadIdx.x;
    const int tx = t & 15, ty = t >> 4;

    const size_t rowbase = (size_t)bh * S_ + i0;
    if (t < 64) { smax[t] = rmax[rowbase + t]; sinv[t] = rinv[rowbase + t]; }
    __syncthreads();

    const float* vb = v + (size_t)b * S_ * E_ + h * D_;
    float* Wrow = Wbuf + rowbase * S_;

    float acc[4][4] = {};
    for (int j0 = 0; j0 < S_; j0 += 64) {
        #pragma unroll
        for (int l = 0; l < 16; l++) {
            int idx = t + l * 256;
            int r = idx >> 6, c = idx & 63;
            float w = Wrow[(size_t)r * S_ + j0 + c];
            float pn = fast_exp(w - smax[r]) * sinv[r];
            Wrow[(size_t)r * S_ + j0 + c] = pn;     // final normalized weight
            Ps[r][c] = pn;
            Vs[r][c] = vb[(size_t)(j0 + r) * E_ + c];
        }
        __syncthreads();
        #pragma unroll 8
        for (int jj = 0; jj < 64; jj++) {
            float a[4], bb[4];
            #pragma unroll
            for (int i = 0; i < 4; i++) a[i]  = Ps[ty * 4 + i][jj];
            #pragma unroll
            for (int j = 0; j < 4; j++) bb[j] = Vs[jj][tx * 4 + j];
            #pragma unroll
            for (int i = 0; i < 4; i++)
                #pragma unroll
                for (int j = 0; j < 4; j++)
                    acc[i][j] = fmaf(a[i], bb[j], acc[i][j]);
        }
        __syncthreads();
    }
    float* cb = ctx + ((size_t)b * S_ + i0) * E_ + h * D_;
    #pragma unroll
    for (int i = 0; i < 4; i++)
        #pragma unroll
        for (int j = 0; j < 4; j++)
            cb[(size_t)(ty * 4 + i) * E_ + tx * 4 + j] = acc[i][j];
}

// ---------------- launch ----------------
extern "C" void kernel_launch(void* const* d_in, const int* in_sizes, int n_in,
                              void* d_out, int out_size)
{
    const float* query = (const float*)d_in[0];
    const float* key   = (const float*)d_in[1];
    const float* value = (const float*)d_in[2];
    const float* Wq    = (const float*)d_in[3];
    const float* bq    = (const float*)d_in[4];
    const float* Wk    = (const float*)d_in[5];
    const float* bk    = (const float*)d_in[6];
    const float* Wv    = (const float*)d_in[7];
    const float* bv    = (const float*)d_in[8];
    const float* Wo    = (const float*)d_in[9];
    const float* bo    = (const float*)d_in[10];

    float* out  = (float*)d_out;                       // [B,S,E] attn_output
    float* Wbuf = out + (size_t)M_ * E_;               // [B,H,S,S] attn_weights

    float *gq, *gk, *gv, *gctx, *grm, *gri;
    cudaGetSymbolAddress((void**)&gq,   g_q);
    cudaGetSymbolAddress((void**)&gk,   g_k);
    cudaGetSymbolAddress((void**)&gv,   g_v);
    cudaGetSymbolAddress((void**)&gctx, g_ctx);
    cudaGetSymbolAddress((void**)&grm,  g_rmax);
    cudaGetSymbolAddress((void**)&gri,  g_rinv);

    dim3 gproj(E_ / GBN, M_ / GBM);
    gemm_bias_kernel<<<gproj, 256>>>(query, Wq, bq, gq, M_, E_, QD_);
    gemm_bias_kernel<<<gproj, 256>>>(key,   Wk, bk, gk, M_, E_, KD_);
    gemm_bias_kernel<<<gproj, 256>>>(value, Wv, bv, gv, M_, E_, VD_);

    scores_kernel<<<dim3(S_ / 64, S_ / 64, BH_), 256>>>(gq, gk, Wbuf);

    stats_kernel<<<BH_ * S_, 256>>>(Wbuf, grm, gri);

    av_kernel<<<dim3(S_ / 64, BH_), 256>>>(Wbuf, gv, gctx, grm, gri);

    gemm_bias_kernel<<<gproj, 256>>>(gctx, Wo, bo, out, M_, E_, E_);
}

// round 6
// speedup vs baseline: 3.1897x; 3.1897x over previous
#include <cuda_runtime.h>
#include <cuda_bf16.h>
#include <cstdint>

#define B_   4
#define S_   2048
#define E_   1024
#define H_   16
#define D_   64
#define QD_  1024
#define KD_  768
#define VD_  768
#define M_   (B_ * S_)          // 8192
#define BH_  (B_ * H_)          // 64

// ---------------- device scratch (no allocations allowed) ----------------
__device__ float g_q[M_ * E_];
__device__ float g_k[M_ * E_];
__device__ float g_v[M_ * E_];
__device__ float g_ctx[M_ * E_];
__device__ __align__(16) __nv_bfloat16 g_Ahi[M_ * E_];
__device__ __align__(16) __nv_bfloat16 g_Alo[M_ * E_];
__device__ __align__(16) __nv_bfloat16 g_Whi[E_ * E_];
__device__ __align__(16) __nv_bfloat16 g_Wlo[E_ * E_];
__device__ __align__(16) __nv_bfloat16 g_qhi[BH_ * S_ * D_];
__device__ __align__(16) __nv_bfloat16 g_qlo[BH_ * S_ * D_];
__device__ __align__(16) __nv_bfloat16 g_khi[BH_ * S_ * D_];
__device__ __align__(16) __nv_bfloat16 g_klo[BH_ * S_ * D_];
__device__ __align__(16) __nv_bfloat16 g_vthi[BH_ * D_ * S_];
__device__ __align__(16) __nv_bfloat16 g_vtlo[BH_ * D_ * S_];

// ======================= helpers ============================
__device__ __forceinline__ uint32_t smem_u32(const void* p) {
    uint32_t a;
    asm("{ .reg .u64 t; cvta.to.shared.u64 t, %1; cvt.u32.u64 %0, t; }"
        : "=r"(a) : "l"(p));
    return a;
}
__device__ __forceinline__ void cp16(uint32_t dst, const void* src) {
    asm volatile("cp.async.cg.shared.global [%0], [%1], 16;" :: "r"(dst), "l"(src));
}
#define LDSM4(R, addr) \
    asm volatile("ldmatrix.sync.aligned.m8n8.x4.shared.b16 {%0,%1,%2,%3}, [%4];" \
                 : "=r"((R)[0]), "=r"((R)[1]), "=r"((R)[2]), "=r"((R)[3]) : "r"(addr))
#define MMA16816(c, a, b0, b1) \
    asm volatile("mma.sync.aligned.m16n8k16.row.col.f32.bf16.bf16.f32 " \
                 "{%0,%1,%2,%3}, {%4,%5,%6,%7}, {%8,%9}, {%0,%1,%2,%3};" \
                 : "+f"((c)[0]), "+f"((c)[1]), "+f"((c)[2]), "+f"((c)[3]) \
                 : "r"((a)[0]), "r"((a)[1]), "r"((a)[2]), "r"((a)[3]), "r"(b0), "r"(b1))

__device__ __forceinline__ uint32_t pack_bf2(float a, float b) {
    __nv_bfloat162 t = __floats2bfloat162_rn(a, b);
    return *(uint32_t*)&t;
}

__device__ __forceinline__ float fast_exp(float x) {
    float t = x * 1.44269504088896341f;
    t = fmaxf(t, -125.0f);
    float r = t + 12582912.0f;
    int   n = __float_as_int(r) - 0x4B400000;
    float f = t - (r - 12582912.0f);
    float p = 1.33336498e-3f;
    p = fmaf(p, f, 9.61011466e-3f);
    p = fmaf(p, f, 5.55036595e-2f);
    p = fmaf(p, f, 2.40226510e-1f);
    p = fmaf(p, f, 6.93147182e-1f);
    p = fmaf(p, f, 1.0f);
    return __int_as_float((n + 127) << 23) * p;
}

// ================= generic hi/lo split tensor-core GEMM ==================
// C[M,N] = alpha*(Ahi@Bhi^T + Ahi@Blo^T + Alo@Bhi^T) + bias
// A: [M,K] row-major (bf16 hi/lo pair, or fp32 split in-kernel if AF32).
// B: [N,K] row-major bf16 hi/lo. Tiles: 128 x BN, BK=32, 2-stage cp.async.
// grid = (N/BN, M/128, batch). C base = C + (z/zdiv)*sCo + (z%zdiv)*sCi.
template<int BN, bool AF32>
__global__ __launch_bounds__(256) void hilo_gemm(
    const void* __restrict__ Ahi_, const void* __restrict__ Alo_,
    const __nv_bfloat16* __restrict__ Bhi_, const __nv_bfloat16* __restrict__ Blo_,
    const float* __restrict__ bias, float* __restrict__ C,
    int K, int ldA, int ldB, int ldC,
    long long strideA, long long strideB,
    long long sCo, long long sCi, int zdiv, float alpha)
{
    constexpr int NI  = BN / 16;           // n-mma tiles per warp (warpN=2)
    constexpr int SSA = 128 * 80;          // one A tile bytes (128 rows * 40 elem * 2B)
    constexpr int BOF = BN * 80;           // one B tile bytes
    constexpr int SS  = 2 * SSA + 2 * BOF; // stage bytes
    extern __shared__ __align__(16) char smem[];
    const uint32_t sbase = smem_u32(smem);

    const int tid  = threadIdx.x;
    const int lane = tid & 31;
    const int wid  = tid >> 5;
    const int m0w  = (wid >> 1) * 32;
    const int n0w  = (wid & 1) * (BN / 2);
    const int m0   = blockIdx.y * 128;
    const int n0   = blockIdx.x * BN;
    const size_t z = blockIdx.z;

    const __nv_bfloat16* Ah = nullptr;
    const __nv_bfloat16* Al = nullptr;
    const float* Af = nullptr;
    if (AF32) {
        Af = (const float*)Ahi_ + z * strideA + (size_t)m0 * ldA;
    } else {
        Ah = (const __nv_bfloat16*)Ahi_ + z * strideA + (size_t)m0 * ldA;
        Al = (const __nv_bfloat16*)Alo_ + z * strideA + (size_t)m0 * ldA;
    }
    const __nv_bfloat16* Bh = Bhi_ + z * strideB + (size_t)n0 * ldB;
    const __nv_bfloat16* Bl = Blo_ + z * strideB + (size_t)n0 * ldB;

    const int T = K / 32;
    float acc[2][NI][4];
    #pragma unroll
    for (int i = 0; i < 2; i++)
        #pragma unroll
        for (int j = 0; j < NI; j++)
            #pragma unroll
            for (int q = 0; q < 4; q++) acc[i][j][q] = 0.0f;

    auto load_stage = [&](int it) {
        const int st = it & 1;
        const int k0 = it * 32;
        const uint32_t sb = sbase + st * SS;
        // B tiles (always cp.async)
        #pragma unroll
        for (int c = tid; c < BN * 8; c += 256) {
            int tile = (c >= BN * 4) ? 1 : 0;
            int cc   = c - tile * BN * 4;
            int r    = cc >> 2, seg = cc & 3;
            const __nv_bfloat16* src = (tile ? Bl : Bh) + (size_t)r * ldB + k0 + seg * 8;
            cp16(sb + 2 * SSA + tile * BOF + r * 80 + seg * 16, src);
        }
        if (AF32) {
            char* sp = smem + st * SS;
            #pragma unroll
            for (int c = tid; c < 1024; c += 256) {
                int r = c >> 3, seg = c & 7;
                float4 v = *(const float4*)(Af + (size_t)r * ldA + k0 + seg * 4);
                __nv_bfloat16 hx = __float2bfloat16(v.x);
                __nv_bfloat16 hy = __float2bfloat16(v.y);
                __nv_bfloat16 hz = __float2bfloat16(v.z);
                __nv_bfloat16 hw = __float2bfloat16(v.w);
                uint32_t h01 = pack_bf2(v.x, v.y);   // rn-packed hi
                uint32_t h23 = pack_bf2(v.z, v.w);
                // recompute hi consistently with packed value
                __nv_bfloat162 H01 = *(__nv_bfloat162*)&h01;
                __nv_bfloat162 H23 = *(__nv_bfloat162*)&h23;
                uint32_t l01 = pack_bf2(v.x - __bfloat162float(H01.x),
                                        v.y - __bfloat162float(H01.y));
                uint32_t l23 = pack_bf2(v.z - __bfloat162float(H23.x),
                                        v.w - __bfloat162float(H23.y));
                (void)hx; (void)hy; (void)hz; (void)hw;
                *(uint32_t*)(sp + r * 80 + seg * 8)           = h01;
                *(uint32_t*)(sp + r * 80 + seg * 8 + 4)       = h23;
                *(uint32_t*)(sp + SSA + r * 80 + seg * 8)     = l01;
                *(uint32_t*)(sp + SSA + r * 80 + seg * 8 + 4) = l23;
            }
        } else {
            #pragma unroll
            for (int c = tid; c < 1024; c += 256) {
                int tile = c >> 9;
                int r = (c >> 2) & 127, seg = c & 3;
                const __nv_bfloat16* src = (tile ? Al : Ah) + (size_t)r * ldA + k0 + seg * 8;
                cp16(sb + tile * SSA + r * 80 + seg * 16, src);
            }
        }
    };

    load_stage(0);
    asm volatile("cp.async.commit_group;" ::: "memory");

    for (int it = 0; it < T; it++) {
        if (it + 1 < T) {
            load_stage(it + 1);
            asm volatile("cp.async.commit_group;" ::: "memory");
            asm volatile("cp.async.wait_group 1;" ::: "memory");
        } else {
            asm volatile("cp.async.wait_group 0;" ::: "memory");
        }
        __syncthreads();

        const uint32_t sA = sbase + (it & 1) * SS;
        const uint32_t sB = sA + 2 * SSA;
        #pragma unroll
        for (int kk = 0; kk < 2; kk++) {
            uint32_t ah[2][4], al[2][4];
            #pragma unroll
            for (int mi = 0; mi < 2; mi++) {
                uint32_t addr = sA + ((m0w + mi * 16 + (lane & 15)) * 40
                                      + kk * 16 + ((lane >> 4) << 3)) * 2;
                LDSM4(ah[mi], addr);
                LDSM4(al[mi], addr + SSA);
            }
            uint32_t bh[NI][2], bl[NI][2];
            #pragma unroll
            for (int nj = 0; nj < NI / 2; nj++) {
                uint32_t row = n0w + nj * 16 + (lane & 7) + ((lane >> 4) << 3);
                uint32_t col = kk * 16 + (((lane >> 3) & 1) << 3);
                uint32_t addr = sB + (row * 40 + col) * 2;
                uint32_t t4[4];
                LDSM4(t4, addr);
                bh[2 * nj][0] = t4[0]; bh[2 * nj][1] = t4[1];
                bh[2 * nj + 1][0] = t4[2]; bh[2 * nj + 1][1] = t4[3];
                LDSM4(t4, addr + BOF);
                bl[2 * nj][0] = t4[0]; bl[2 * nj][1] = t4[1];
                bl[2 * nj + 1][0] = t4[2]; bl[2 * nj + 1][1] = t4[3];
            }
            #pragma unroll
            for (int mi = 0; mi < 2; mi++)
                #pragma unroll
                for (int ni = 0; ni < NI; ni++) {
                    MMA16816(acc[mi][ni], ah[mi], bh[ni][0], bh[ni][1]);
                    MMA16816(acc[mi][ni], ah[mi], bl[ni][0], bl[ni][1]);
                    MMA16816(acc[mi][ni], al[mi], bh[ni][0], bh[ni][1]);
                }
        }
        __syncthreads();
    }

    // epilogue
    float* Cz = C + (z / zdiv) * sCo + (z % zdiv) * sCi;
    #pragma unroll
    for (int mi = 0; mi < 2; mi++)
        #pragma unroll
        for (int ni = 0; ni < NI; ni++) {
            int row = m0 + m0w + mi * 16 + (lane >> 2);
            int col = n0 + n0w + ni * 8 + ((lane & 3) << 1);
            float b0 = bias ? __ldg(bias + col) : 0.0f;
            float b1 = bias ? __ldg(bias + col + 1) : 0.0f;
            Cz[(size_t)row * ldC + col]           = acc[mi][ni][0] * alpha + b0;
            Cz[(size_t)row * ldC + col + 1]       = acc[mi][ni][1] * alpha + b1;
            Cz[(size_t)(row + 8) * ldC + col]     = acc[mi][ni][2] * alpha + b0;
            Cz[(size_t)(row + 8) * ldC + col + 1] = acc[mi][ni][3] * alpha + b1;
        }
}

// ================= conversions ===========================================
__global__ __launch_bounds__(256) void conv_hilo_kernel(
    const float* __restrict__ in, __nv_bfloat16* __restrict__ hi,
    __nv_bfloat16* __restrict__ lo, int n)
{
    int i = blockIdx.x * 256 + threadIdx.x;
    if (i < n) {
        float x = in[i];
        __nv_bfloat16 h = __float2bfloat16(x);
        hi[i] = h;
        lo[i] = __float2bfloat16(x - __bfloat162float(h));
    }
}

// W[K,N] fp32 -> Wt[N,K] bf16 hi/lo
__global__ __launch_bounds__(256) void transconv_kernel(
    const float* __restrict__ W, __nv_bfloat16* __restrict__ hi,
    __nv_bfloat16* __restrict__ lo, int K, int N)
{
    __shared__ float t[32][33];
    const int k0 = blockIdx.y * 32, n0 = blockIdx.x * 32;
    const int tx = threadIdx.x & 31, ty = threadIdx.x >> 5;
    #pragma unroll
    for (int i = 0; i < 32; i += 8)
        t[ty + i][tx] = W[(size_t)(k0 + ty + i) * N + n0 + tx];
    __syncthreads();
    #pragma unroll
    for (int i = 0; i < 32; i += 8) {
        float x = t[tx][ty + i];
        __nv_bfloat16 h = __float2bfloat16(x);
        size_t o = (size_t)(n0 + ty + i) * K + k0 + tx;
        hi[o] = h;
        lo[o] = __float2bfloat16(x - __bfloat162float(h));
    }
}

// [b][s][h*64+d] fp32 -> [bh][s][d] bf16 hi/lo
__global__ __launch_bounds__(256) void headconv_kernel(
    const float* __restrict__ src, __nv_bfloat16* __restrict__ hi,
    __nv_bfloat16* __restrict__ lo)
{
    int idx = blockIdx.x * 256 + threadIdx.x;
    int d = idx & 63, h = (idx >> 6) & 15, s = (idx >> 10) & 2047, b = idx >> 21;
    float x = src[idx];
    __nv_bfloat16 hh = __float2bfloat16(x);
    size_t o = (((size_t)(b * 16 + h)) * S_ + s) * D_ + d;
    hi[o] = hh;
    lo[o] = __float2bfloat16(x - __bfloat162float(hh));
}

// [b][s][h*64+d] fp32 -> [bh][d][s] bf16 hi/lo (transposed for AV B operand)
__global__ __launch_bounds__(256) void vconvt_kernel(
    const float* __restrict__ v, __nv_bfloat16* __restrict__ hi,
    __nv_bfloat16* __restrict__ lo)
{
    __shared__ float t[32][33];
    const int bh = blockIdx.z, b = bh >> 4, h = bh & 15;
    const int s0 = blockIdx.x * 32, d0 = blockIdx.y * 32;
    const int tx = threadIdx.x & 31, ty = threadIdx.x >> 5;
    #pragma unroll
    for (int i = 0; i < 32; i += 8)
        t[ty + i][tx] = v[((size_t)b * S_ + s0 + ty + i) * E_ + h * D_ + d0 + tx];
    __syncthreads();
    #pragma unroll
    for (int i = 0; i < 32; i += 8) {
        float x = t[tx][ty + i];
        __nv_bfloat16 hh = __float2bfloat16(x);
        size_t o = ((size_t)bh * D_ + d0 + ty + i) * S_ + s0 + tx;
        hi[o] = hh;
        lo[o] = __float2bfloat16(x - __bfloat162float(hh));
    }
}

// ---------------- fused softmax row pass (in-place) ----------------------
__global__ __launch_bounds__(256) void softmax_kernel(float* __restrict__ Wbuf)
{
    const size_t row = blockIdx.x;
    float* p = Wbuf + row * S_;
    const int t = threadIdx.x;
    __shared__ float red[8];
    __shared__ float s_m, s_r;

    float v[8];
    float m = -1e30f;
    #pragma unroll
    for (int i = 0; i < 8; i++) { v[i] = p[t + i * 256]; m = fmaxf(m, v[i]); }
    #pragma unroll
    for (int o = 16; o; o >>= 1) m = fmaxf(m, __shfl_xor_sync(0xFFFFFFFFu, m, o));
    if ((t & 31) == 0) red[t >> 5] = m;
    __syncthreads();
    if (t == 0) {
        float mm = red[0];
        #pragma unroll
        for (int i = 1; i < 8; i++) mm = fmaxf(mm, red[i]);
        s_m = mm;
    }
    __syncthreads();
    m = s_m;

    float s = 0.0f;
    #pragma unroll
    for (int i = 0; i < 8; i++) { v[i] = fast_exp(v[i] - m); s += v[i]; }
    #pragma unroll
    for (int o = 16; o; o >>= 1) s += __shfl_xor_sync(0xFFFFFFFFu, s, o);
    if ((t & 31) == 0) red[t >> 5] = s;
    __syncthreads();
    if (t == 0) {
        float tot = 0.0f;
        #pragma unroll
        for (int i = 0; i < 8; i++) tot += red[i];
        s_r = 1.0f / tot;
    }
    __syncthreads();
    const float rinv = s_r;
    #pragma unroll
    for (int i = 0; i < 8; i++) p[t + i * 256] = v[i] * rinv;
}

// ---------------- launch ----------------
extern "C" void kernel_launch(void* const* d_in, const int* in_sizes, int n_in,
                              void* d_out, int out_size)
{
    const float* query = (const float*)d_in[0];
    const float* key   = (const float*)d_in[1];
    const float* value = (const float*)d_in[2];
    const float* Wq    = (const float*)d_in[3];
    const float* bq    = (const float*)d_in[4];
    const float* Wk    = (const float*)d_in[5];
    const float* bk    = (const float*)d_in[6];
    const float* Wv    = (const float*)d_in[7];
    const float* bv    = (const float*)d_in[8];
    const float* Wo    = (const float*)d_in[9];
    const float* bo    = (const float*)d_in[10];

    float* out  = (float*)d_out;                 // [B,S,E]
    float* Wbuf = out + (size_t)M_ * E_;         // [B,H,S,S]

    float *gq, *gk, *gv, *gctx;
    __nv_bfloat16 *ahi, *alo, *whi, *wlo, *qhi, *qlo, *khi, *klo, *vthi, *vtlo;
    cudaGetSymbolAddress((void**)&gq,   g_q);
    cudaGetSymbolAddress((void**)&gk,   g_k);
    cudaGetSymbolAddress((void**)&gv,   g_v);
    cudaGetSymbolAddress((void**)&gctx, g_ctx);
    cudaGetSymbolAddress((void**)&ahi,  g_Ahi);
    cudaGetSymbolAddress((void**)&alo,  g_Alo);
    cudaGetSymbolAddress((void**)&whi,  g_Whi);
    cudaGetSymbolAddress((void**)&wlo,  g_Wlo);
    cudaGetSymbolAddress((void**)&qhi,  g_qhi);
    cudaGetSymbolAddress((void**)&qlo,  g_qlo);
    cudaGetSymbolAddress((void**)&khi,  g_khi);
    cudaGetSymbolAddress((void**)&klo,  g_klo);
    cudaGetSymbolAddress((void**)&vthi, g_vthi);
    cudaGetSymbolAddress((void**)&vtlo, g_vtlo);

    const int SMEM_P = 2 * (2 * 128 * 80 + 2 * 128 * 80);  // BN=128: 81920
    const int SMEM_A = 2 * (2 * 128 * 80 + 2 * 64 * 80);   // BN=64:  61440
    cudaFuncSetAttribute(hilo_gemm<128, false>,
                         cudaFuncAttributeMaxDynamicSharedMemorySize, SMEM_P);
    cudaFuncSetAttribute(hilo_gemm<64, true>,
                         cudaFuncAttributeMaxDynamicSharedMemorySize, SMEM_A);

    // ---- projections ----
    conv_hilo_kernel<<<(M_ * QD_) / 256, 256>>>(query, ahi, alo, M_ * QD_);
    transconv_kernel<<<dim3(E_ / 32, QD_ / 32), 256>>>(Wq, whi, wlo, QD_, E_);
    hilo_gemm<128, false><<<dim3(E_ / 128, M_ / 128, 1), 256, SMEM_P>>>(
        ahi, alo, whi, wlo, bq, gq, QD_, QD_, QD_, E_, 0, 0, 0, 0, 1, 1.0f);

    conv_hilo_kernel<<<(M_ * KD_) / 256, 256>>>(key, ahi, alo, M_ * KD_);
    transconv_kernel<<<dim3(E_ / 32, KD_ / 32), 256>>>(Wk, whi, wlo, KD_, E_);
    hilo_gemm<128, false><<<dim3(E_ / 128, M_ / 128, 1), 256, SMEM_P>>>(
        ahi, alo, whi, wlo, bk, gk, KD_, KD_, KD_, E_, 0, 0, 0, 0, 1, 1.0f);

    conv_hilo_kernel<<<(M_ * VD_) / 256, 256>>>(value, ahi, alo, M_ * VD_);
    transconv_kernel<<<dim3(E_ / 32, VD_ / 32), 256>>>(Wv, whi, wlo, VD_, E_);
    hilo_gemm<128, false><<<dim3(E_ / 128, M_ / 128, 1), 256, SMEM_P>>>(
        ahi, alo, whi, wlo, bv, gv, VD_, VD_, VD_, E_, 0, 0, 0, 0, 1, 1.0f);

    // ---- head-major conversions ----
    headconv_kernel<<<(M_ * E_) / 256, 256>>>(gq, qhi, qlo);
    headconv_kernel<<<(M_ * E_) / 256, 256>>>(gk, khi, klo);
    vconvt_kernel<<<dim3(S_ / 32, D_ / 32, BH_), 256>>>(gv, vthi, vtlo);

    // ---- scores: Wbuf[bh][i][j] = 0.125 * q.k ----
    hilo_gemm<128, false><<<dim3(S_ / 128, S_ / 128, BH_), 256, SMEM_P>>>(
        qhi, qlo, khi, klo, nullptr, Wbuf, D_, D_, D_, S_,
        (long long)S_ * D_, (long long)S_ * D_,
        (long long)S_ * S_, 0, 1, 0.125f);

    // ---- softmax in-place ----
    softmax_kernel<<<(size_t)BH_ * S_, 256>>>(Wbuf);

    // ---- AV: ctx[b][s][h*64+d] = P @ V ----
    hilo_gemm<64, true><<<dim3(1, S_ / 128, BH_), 256, SMEM_A>>>(
        Wbuf, nullptr, vthi, vtlo, nullptr, gctx, S_, S_, S_, E_,
        (long long)S_ * S_, (long long)D_ * S_,
        (long long)S_ * E_, (long long)D_, 16, 1.0f);

    // ---- output projection ----
    conv_hilo_kernel<<<(M_ * E_) / 256, 256>>>(gctx, ahi, alo, M_ * E_);
    transconv_kernel<<<dim3(E_ / 32, E_ / 32), 256>>>(Wo, whi, wlo, E_, E_);
    hilo_gemm<128, false><<<dim3(E_ / 128, M_ / 128, 1), 256, SMEM_P>>>(
        ahi, alo, whi, wlo, bo, out, E_, E_, E_, E_, 0, 0, 0, 0, 1, 1.0f);
}

// round 7
// speedup vs baseline: 3.3867x; 1.0618x over previous
#include <cuda_runtime.h>
#include <cuda_bf16.h>
#include <cstdint>

#define B_   4
#define S_   2048
#define E_   1024
#define H_   16
#define D_   64
#define QD_  1024
#define KD_  768
#define VD_  768
#define M_   (B_ * S_)          // 8192
#define BH_  (B_ * H_)          // 64

// ---------------- device scratch (no allocations allowed) ----------------
__device__ __align__(16) __nv_bfloat16 g_Ahi[M_ * E_];
__device__ __align__(16) __nv_bfloat16 g_Alo[M_ * E_];
__device__ __align__(16) __nv_bfloat16 g_Whi[E_ * E_];
__device__ __align__(16) __nv_bfloat16 g_Wlo[E_ * E_];
__device__ __align__(16) __nv_bfloat16 g_qhi[BH_ * S_ * D_];
__device__ __align__(16) __nv_bfloat16 g_qlo[BH_ * S_ * D_];
__device__ __align__(16) __nv_bfloat16 g_khi[BH_ * S_ * D_];
__device__ __align__(16) __nv_bfloat16 g_klo[BH_ * S_ * D_];
__device__ __align__(16) __nv_bfloat16 g_vhi[BH_ * S_ * D_];
__device__ __align__(16) __nv_bfloat16 g_vlo[BH_ * S_ * D_];
__device__ __align__(16) __nv_bfloat16 g_vthi[BH_ * D_ * S_];
__device__ __align__(16) __nv_bfloat16 g_vtlo[BH_ * D_ * S_];

// ======================= helpers ============================
__device__ __forceinline__ uint32_t smem_u32(const void* p) {
    uint32_t a;
    asm("{ .reg .u64 t; cvta.to.shared.u64 t, %1; cvt.u32.u64 %0, t; }"
        : "=r"(a) : "l"(p));
    return a;
}
__device__ __forceinline__ void cp16(uint32_t dst, const void* src) {
    asm volatile("cp.async.cg.shared.global [%0], [%1], 16;" :: "r"(dst), "l"(src));
}
#define LDSM4(R, addr) \
    asm volatile("ldmatrix.sync.aligned.m8n8.x4.shared.b16 {%0,%1,%2,%3}, [%4];" \
                 : "=r"((R)[0]), "=r"((R)[1]), "=r"((R)[2]), "=r"((R)[3]) : "r"(addr))
#define MMA16816(c, a, b0, b1) \
    asm volatile("mma.sync.aligned.m16n8k16.row.col.f32.bf16.bf16.f32 " \
                 "{%0,%1,%2,%3}, {%4,%5,%6,%7}, {%8,%9}, {%0,%1,%2,%3};" \
                 : "+f"((c)[0]), "+f"((c)[1]), "+f"((c)[2]), "+f"((c)[3]) \
                 : "r"((a)[0]), "r"((a)[1]), "r"((a)[2]), "r"((a)[3]), "r"(b0), "r"(b1))

__device__ __forceinline__ uint32_t pack_bf2(float a, float b) {
    __nv_bfloat162 t = __floats2bfloat162_rn(a, b);
    return *(uint32_t*)&t;
}

__device__ __forceinline__ float fast_exp(float x) {
    float t = x * 1.44269504088896341f;
    t = fmaxf(t, -125.0f);
    float r = t + 12582912.0f;
    int   n = __float_as_int(r) - 0x4B400000;
    float f = t - (r - 12582912.0f);
    float p = 1.33336498e-3f;
    p = fmaf(p, f, 9.61011466e-3f);
    p = fmaf(p, f, 5.55036595e-2f);
    p = fmaf(p, f, 2.40226510e-1f);
    p = fmaf(p, f, 6.93147182e-1f);
    p = fmaf(p, f, 1.0f);
    return __int_as_float((n + 127) << 23) * p;
}

// write fp32 pair as bf16 hi/lo pair at bf162-element index o
__device__ __forceinline__ void store_hilo2(
    __nv_bfloat16* Ohi, __nv_bfloat16* Olo, size_t o, float x0, float x1)
{
    __nv_bfloat162 hh = __floats2bfloat162_rn(x0, x1);
    float l0 = x0 - __bfloat162float(hh.x);
    float l1 = x1 - __bfloat162float(hh.y);
    ((__nv_bfloat162*)Ohi)[o] = hh;
    ((__nv_bfloat162*)Olo)[o] = __floats2bfloat162_rn(l0, l1);
}

// ================= generic hi/lo split tensor-core GEMM ==================
// C[M,N] = alpha*(Ahi@Bhi^T + Ahi@Blo^T + Alo@Bhi^T) + bias
// A: [M,K] row-major (bf16 hi/lo pair, or fp32 split in-kernel if AF32).
// B: [N,K] row-major bf16 hi/lo. Tiles: 128 x BN, BK=32, 2-stage cp.async.
// EPI=0: fp32 C (zdiv/sCo/sCi batching).  EPI=1: bf16 hi/lo head-major
// [bh][s][d] (rows are global tokens, cols are h*64+d).  EPI=2: bf16 hi/lo
// row-major [token][E] at column (z%zdiv)*64 + col (AV -> out-proj A).
template<int BN, bool AF32, int EPI>
__global__ __launch_bounds__(256) void hilo_gemm(
    const void* __restrict__ Ahi_, const void* __restrict__ Alo_,
    const __nv_bfloat16* __restrict__ Bhi_, const __nv_bfloat16* __restrict__ Blo_,
    const float* __restrict__ bias, float* __restrict__ C,
    __nv_bfloat16* __restrict__ Ohi, __nv_bfloat16* __restrict__ Olo,
    int K, int ldA, int ldB, int ldC,
    long long strideA, long long strideB,
    long long sCo, long long sCi, int zdiv, float alpha)
{
    constexpr int NI  = BN / 16;
    constexpr int SSA = 128 * 80;
    constexpr int BOF = BN * 80;
    constexpr int SS  = 2 * SSA + 2 * BOF;
    extern __shared__ __align__(16) char smem[];
    const uint32_t sbase = smem_u32(smem);

    const int tid  = threadIdx.x;
    const int lane = tid & 31;
    const int wid  = tid >> 5;
    const int m0w  = (wid >> 1) * 32;
    const int n0w  = (wid & 1) * (BN / 2);
    const int m0   = blockIdx.y * 128;
    const int n0   = blockIdx.x * BN;
    const size_t z = blockIdx.z;

    const __nv_bfloat16* Ah = nullptr;
    const __nv_bfloat16* Al = nullptr;
    const float* Af = nullptr;
    if (AF32) {
        Af = (const float*)Ahi_ + z * strideA + (size_t)m0 * ldA;
    } else {
        Ah = (const __nv_bfloat16*)Ahi_ + z * strideA + (size_t)m0 * ldA;
        Al = (const __nv_bfloat16*)Alo_ + z * strideA + (size_t)m0 * ldA;
    }
    const __nv_bfloat16* Bh = Bhi_ + z * strideB + (size_t)n0 * ldB;
    const __nv_bfloat16* Bl = Blo_ + z * strideB + (size_t)n0 * ldB;

    const int T = K / 32;
    float acc[2][NI][4];
    #pragma unroll
    for (int i = 0; i < 2; i++)
        #pragma unroll
        for (int j = 0; j < NI; j++)
            #pragma unroll
            for (int q = 0; q < 4; q++) acc[i][j][q] = 0.0f;

    auto load_stage = [&](int it) {
        const int st = it & 1;
        const int k0 = it * 32;
        const uint32_t sb = sbase + st * SS;
        #pragma unroll
        for (int c = tid; c < BN * 8; c += 256) {
            int tile = (c >= BN * 4) ? 1 : 0;
            int cc   = c - tile * BN * 4;
            int r    = cc >> 2, seg = cc & 3;
            const __nv_bfloat16* src = (tile ? Bl : Bh) + (size_t)r * ldB + k0 + seg * 8;
            cp16(sb + 2 * SSA + tile * BOF + r * 80 + seg * 16, src);
        }
        if (AF32) {
            char* sp = smem + st * SS;
            #pragma unroll
            for (int c = tid; c < 1024; c += 256) {
                int r = c >> 3, seg = c & 7;
                float4 v = *(const float4*)(Af + (size_t)r * ldA + k0 + seg * 4);
                uint32_t h01 = pack_bf2(v.x, v.y);
                uint32_t h23 = pack_bf2(v.z, v.w);
                __nv_bfloat162 H01 = *(__nv_bfloat162*)&h01;
                __nv_bfloat162 H23 = *(__nv_bfloat162*)&h23;
                uint32_t l01 = pack_bf2(v.x - __bfloat162float(H01.x),
                                        v.y - __bfloat162float(H01.y));
                uint32_t l23 = pack_bf2(v.z - __bfloat162float(H23.x),
                                        v.w - __bfloat162float(H23.y));
                *(uint32_t*)(sp + r * 80 + seg * 8)           = h01;
                *(uint32_t*)(sp + r * 80 + seg * 8 + 4)       = h23;
                *(uint32_t*)(sp + SSA + r * 80 + seg * 8)     = l01;
                *(uint32_t*)(sp + SSA + r * 80 + seg * 8 + 4) = l23;
            }
        } else {
            #pragma unroll
            for (int c = tid; c < 1024; c += 256) {
                int tile = c >> 9;
                int r = (c >> 2) & 127, seg = c & 3;
                const __nv_bfloat16* src = (tile ? Al : Ah) + (size_t)r * ldA + k0 + seg * 8;
                cp16(sb + tile * SSA + r * 80 + seg * 16, src);
            }
        }
    };

    load_stage(0);
    asm volatile("cp.async.commit_group;" ::: "memory");

    for (int it = 0; it < T; it++) {
        if (it + 1 < T) {
            load_stage(it + 1);
            asm volatile("cp.async.commit_group;" ::: "memory");
            asm volatile("cp.async.wait_group 1;" ::: "memory");
        } else {
            asm volatile("cp.async.wait_group 0;" ::: "memory");
        }
        __syncthreads();

        const uint32_t sA = sbase + (it & 1) * SS;
        const uint32_t sB = sA + 2 * SSA;
        #pragma unroll
        for (int kk = 0; kk < 2; kk++) {
            uint32_t ah[2][4], al[2][4];
            #pragma unroll
            for (int mi = 0; mi < 2; mi++) {
                uint32_t addr = sA + ((m0w + mi * 16 + (lane & 15)) * 40
                                      + kk * 16 + ((lane >> 4) << 3)) * 2;
                LDSM4(ah[mi], addr);
                LDSM4(al[mi], addr + SSA);
            }
            uint32_t bh[NI][2], bl[NI][2];
            #pragma unroll
            for (int nj = 0; nj < NI / 2; nj++) {
                uint32_t row = n0w + nj * 16 + (lane & 7) + ((lane >> 4) << 3);
                uint32_t col = kk * 16 + (((lane >> 3) & 1) << 3);
                uint32_t addr = sB + (row * 40 + col) * 2;
                uint32_t t4[4];
                LDSM4(t4, addr);
                bh[2 * nj][0] = t4[0]; bh[2 * nj][1] = t4[1];
                bh[2 * nj + 1][0] = t4[2]; bh[2 * nj + 1][1] = t4[3];
                LDSM4(t4, addr + BOF);
                bl[2 * nj][0] = t4[0]; bl[2 * nj][1] = t4[1];
                bl[2 * nj + 1][0] = t4[2]; bl[2 * nj + 1][1] = t4[3];
            }
            #pragma unroll
            for (int mi = 0; mi < 2; mi++)
                #pragma unroll
                for (int ni = 0; ni < NI; ni++) {
                    MMA16816(acc[mi][ni], ah[mi], bh[ni][0], bh[ni][1]);
                    MMA16816(acc[mi][ni], ah[mi], bl[ni][0], bl[ni][1]);
                    MMA16816(acc[mi][ni], al[mi], bh[ni][0], bh[ni][1]);
                }
        }
        __syncthreads();
    }

    // ---------------- epilogue ----------------
    if (EPI == 0) {
        float* Cz = C + (z / zdiv) * sCo + (z % zdiv) * sCi;
        #pragma unroll
        for (int mi = 0; mi < 2; mi++)
            #pragma unroll
            for (int ni = 0; ni < NI; ni++) {
                int row = m0 + m0w + mi * 16 + (lane >> 2);
                int col = n0 + n0w + ni * 8 + ((lane & 3) << 1);
                float b0 = bias ? __ldg(bias + col) : 0.0f;
                float b1 = bias ? __ldg(bias + col + 1) : 0.0f;
                Cz[(size_t)row * ldC + col]           = acc[mi][ni][0] * alpha + b0;
                Cz[(size_t)row * ldC + col + 1]       = acc[mi][ni][1] * alpha + b1;
                Cz[(size_t)(row + 8) * ldC + col]     = acc[mi][ni][2] * alpha + b0;
                Cz[(size_t)(row + 8) * ldC + col + 1] = acc[mi][ni][3] * alpha + b1;
            }
    } else if (EPI == 1) {
        // head-major bf16 hi/lo: token row -> [b*16+h][s][d]
        #pragma unroll
        for (int mi = 0; mi < 2; mi++)
            #pragma unroll
            for (int ni = 0; ni < NI; ni++) {
                int row = m0 + m0w + mi * 16 + (lane >> 2);
                int col = n0 + n0w + ni * 8 + ((lane & 3) << 1);
                float b0 = bias ? __ldg(bias + col) : 0.0f;
                float b1 = bias ? __ldg(bias + col + 1) : 0.0f;
                int h = col >> 6, d = col & 63;
                #pragma unroll
                for (int rr = 0; rr < 2; rr++) {
                    int r = row + rr * 8;
                    int b = r >> 11, s = r & 2047;
                    size_t o = ((((size_t)(b * 16 + h)) * S_ + s) * D_ + d) >> 1;
                    store_hilo2(Ohi, Olo, o,
                                acc[mi][ni][rr * 2 + 0] + b0,
                                acc[mi][ni][rr * 2 + 1] + b1);
                }
            }
    } else {
        // EPI == 2: AV ctx -> row-major [token][E] bf16 hi/lo at col h*64+d
        const int b = (int)z / zdiv, h = (int)z % zdiv;
        #pragma unroll
        for (int mi = 0; mi < 2; mi++)
            #pragma unroll
            for (int ni = 0; ni < NI; ni++) {
                int srow = m0 + m0w + mi * 16 + (lane >> 2);
                int col  = n0 + n0w + ni * 8 + ((lane & 3) << 1);
                #pragma unroll
                for (int rr = 0; rr < 2; rr++) {
                    int s = srow + rr * 8;
                    size_t token = (size_t)b * S_ + s;
                    size_t o = (token * E_ + h * D_ + col) >> 1;
                    store_hilo2(Ohi, Olo, o,
                                acc[mi][ni][rr * 2 + 0],
                                acc[mi][ni][rr * 2 + 1]);
                }
            }
    }
}

// ================= conversions ===========================================
// vectorized fp32 -> bf16 hi/lo (4 elems/thread)
__global__ __launch_bounds__(256) void conv_hilo4_kernel(
    const float4* __restrict__ in, __nv_bfloat162* __restrict__ hi,
    __nv_bfloat162* __restrict__ lo, int n4)
{
    int i = blockIdx.x * 256 + threadIdx.x;
    if (i < n4) {
        float4 v = in[i];
        __nv_bfloat162 h01 = __floats2bfloat162_rn(v.x, v.y);
        __nv_bfloat162 h23 = __floats2bfloat162_rn(v.z, v.w);
        hi[2 * i]     = h01;
        hi[2 * i + 1] = h23;
        lo[2 * i]     = __floats2bfloat162_rn(v.x - __bfloat162float(h01.x),
                                              v.y - __bfloat162float(h01.y));
        lo[2 * i + 1] = __floats2bfloat162_rn(v.z - __bfloat162float(h23.x),
                                              v.w - __bfloat162float(h23.y));
    }
}

// W[K,N] fp32 -> Wt[N,K] bf16 hi/lo
__global__ __launch_bounds__(256) void transconv_kernel(
    const float* __restrict__ W, __nv_bfloat16* __restrict__ hi,
    __nv_bfloat16* __restrict__ lo, int K, int N)
{
    __shared__ float t[32][33];
    const int k0 = blockIdx.y * 32, n0 = blockIdx.x * 32;
    const int tx = threadIdx.x & 31, ty = threadIdx.x >> 5;
    #pragma unroll
    for (int i = 0; i < 32; i += 8)
        t[ty + i][tx] = W[(size_t)(k0 + ty + i) * N + n0 + tx];
    __syncthreads();
    #pragma unroll
    for (int i = 0; i < 32; i += 8) {
        float x = t[tx][ty + i];
        __nv_bfloat16 h = __float2bfloat16(x);
        size_t o = (size_t)(n0 + ty + i) * K + k0 + tx;
        hi[o] = h;
        lo[o] = __float2bfloat16(x - __bfloat162float(h));
    }
}

// [bh][s][d] bf16 -> [bh][d][s] bf16 (hi and lo together)
__global__ __launch_bounds__(256) void transpose_hl_kernel(
    const __nv_bfloat16* __restrict__ hi_in, const __nv_bfloat16* __restrict__ lo_in,
    __nv_bfloat16* __restrict__ hi_out, __nv_bfloat16* __restrict__ lo_out)
{
    __shared__ __nv_bfloat16 th[32][33];
    __shared__ __nv_bfloat16 tl[32][33];
    const int bh = blockIdx.z;
    const int s0 = blockIdx.x * 32, d0 = blockIdx.y * 32;
    const int tx = threadIdx.x & 31, ty = threadIdx.x >> 5;
    #pragma unroll
    for (int i = 0; i < 32; i += 8) {
        size_t src = ((size_t)bh * S_ + s0 + ty + i) * D_ + d0 + tx;
        th[ty + i][tx] = hi_in[src];
        tl[ty + i][tx] = lo_in[src];
    }
    __syncthreads();
    #pragma unroll
    for (int i = 0; i < 32; i += 8) {
        size_t dst = ((size_t)bh * D_ + d0 + ty + i) * S_ + s0 + tx;
        hi_out[dst] = th[tx][ty + i];
        lo_out[dst] = tl[tx][ty + i];
    }
}

// ---------------- fused softmax row pass (in-place, float4) --------------
__global__ __launch_bounds__(256) void softmax_kernel(float* __restrict__ Wbuf)
{
    const size_t row = blockIdx.x;
    float4* p = (float4*)(Wbuf + row * S_);
    const int t = threadIdx.x;
    __shared__ float red[8];
    __shared__ float s_m, s_r;

    float4 va = p[t];
    float4 vb = p[t + 256];
    float m = fmaxf(fmaxf(fmaxf(va.x, va.y), fmaxf(va.z, va.w)),
                    fmaxf(fmaxf(vb.x, vb.y), fmaxf(vb.z, vb.w)));
    #pragma unroll
    for (int o = 16; o; o >>= 1) m = fmaxf(m, __shfl_xor_sync(0xFFFFFFFFu, m, o));
    if ((t & 31) == 0) red[t >> 5] = m;
    __syncthreads();
    if (t == 0) {
        float mm = red[0];
        #pragma unroll
        for (int i = 1; i < 8; i++) mm = fmaxf(mm, red[i]);
        s_m = mm;
    }
    __syncthreads();
    m = s_m;

    va.x = fast_exp(va.x - m); va.y = fast_exp(va.y - m);
    va.z = fast_exp(va.z - m); va.w = fast_exp(va.w - m);
    vb.x = fast_exp(vb.x - m); vb.y = fast_exp(vb.y - m);
    vb.z = fast_exp(vb.z - m); vb.w = fast_exp(vb.w - m);
    float s = va.x + va.y + va.z + va.w + vb.x + vb.y + vb.z + vb.w;
    #pragma unroll
    for (int o = 16; o; o >>= 1) s += __shfl_xor_sync(0xFFFFFFFFu, s, o);
    if ((t & 31) == 0) red[t >> 5] = s;
    __syncthreads();
    if (t == 0) {
        float tot = 0.0f;
        #pragma unroll
        for (int i = 0; i < 8; i++) tot += red[i];
        s_r = 1.0f / tot;
    }
    __syncthreads();
    const float r = s_r;
    va.x *= r; va.y *= r; va.z *= r; va.w *= r;
    vb.x *= r; vb.y *= r; vb.z *= r; vb.w *= r;
    p[t] = va;
    p[t + 256] = vb;
}

// ---------------- launch ----------------
extern "C" void kernel_launch(void* const* d_in, const int* in_sizes, int n_in,
                              void* d_out, int out_size)
{
    const float* query = (const float*)d_in[0];
    const float* key   = (const float*)d_in[1];
    const float* value = (const float*)d_in[2];
    const float* Wq    = (const float*)d_in[3];
    const float* bq    = (const float*)d_in[4];
    const float* Wk    = (const float*)d_in[5];
    const float* bk    = (const float*)d_in[6];
    const float* Wv    = (const float*)d_in[7];
    const float* bv    = (const float*)d_in[8];
    const float* Wo    = (const float*)d_in[9];
    const float* bo    = (const float*)d_in[10];

    float* out  = (float*)d_out;                 // [B,S,E]
    float* Wbuf = out + (size_t)M_ * E_;         // [B,H,S,S]

    __nv_bfloat16 *ahi, *alo, *whi, *wlo, *qhi, *qlo, *khi, *klo;
    __nv_bfloat16 *vhi, *vlo, *vthi, *vtlo;
    cudaGetSymbolAddress((void**)&ahi,  g_Ahi);
    cudaGetSymbolAddress((void**)&alo,  g_Alo);
    cudaGetSymbolAddress((void**)&whi,  g_Whi);
    cudaGetSymbolAddress((void**)&wlo,  g_Wlo);
    cudaGetSymbolAddress((void**)&qhi,  g_qhi);
    cudaGetSymbolAddress((void**)&qlo,  g_qlo);
    cudaGetSymbolAddress((void**)&khi,  g_khi);
    cudaGetSymbolAddress((void**)&klo,  g_klo);
    cudaGetSymbolAddress((void**)&vhi,  g_vhi);
    cudaGetSymbolAddress((void**)&vlo,  g_vlo);
    cudaGetSymbolAddress((void**)&vthi, g_vthi);
    cudaGetSymbolAddress((void**)&vtlo, g_vtlo);

    const int SMEM_P = 2 * (2 * 128 * 80 + 2 * 128 * 80);  // BN=128: 81920
    const int SMEM_A = 2 * (2 * 128 * 80 + 2 * 64 * 80);   // BN=64:  61440
    cudaFuncSetAttribute(hilo_gemm<128, false, 0>,
                         cudaFuncAttributeMaxDynamicSharedMemorySize, SMEM_P);
    cudaFuncSetAttribute(hilo_gemm<128, false, 1>,
                         cudaFuncAttributeMaxDynamicSharedMemorySize, SMEM_P);
    cudaFuncSetAttribute(hilo_gemm<64, true, 2>,
                         cudaFuncAttributeMaxDynamicSharedMemorySize, SMEM_A);

    // ---- projections (write head-major bf16 hi/lo directly) ----
    conv_hilo4_kernel<<<(M_ * QD_ / 4 + 255) / 256, 256>>>(
        (const float4*)query, (__nv_bfloat162*)ahi, (__nv_bfloat162*)alo, M_ * QD_ / 4);
    transconv_kernel<<<dim3(E_ / 32, QD_ / 32), 256>>>(Wq, whi, wlo, QD_, E_);
    hilo_gemm<128, false, 1><<<dim3(E_ / 128, M_ / 128, 1), 256, SMEM_P>>>(
        ahi, alo, whi, wlo, bq, nullptr, qhi, qlo,
        QD_, QD_, QD_, E_, 0, 0, 0, 0, 1, 1.0f);

    conv_hilo4_kernel<<<(M_ * KD_ / 4 + 255) / 256, 256>>>(
        (const float4*)key, (__nv_bfloat162*)ahi, (__nv_bfloat162*)alo, M_ * KD_ / 4);
    transconv_kernel<<<dim3(E_ / 32, KD_ / 32), 256>>>(Wk, whi, wlo, KD_, E_);
    hilo_gemm<128, false, 1><<<dim3(E_ / 128, M_ / 128, 1), 256, SMEM_P>>>(
        ahi, alo, whi, wlo, bk, nullptr, khi, klo,
        KD_, KD_, KD_, E_, 0, 0, 0, 0, 1, 1.0f);

    conv_hilo4_kernel<<<(M_ * VD_ / 4 + 255) / 256, 256>>>(
        (const float4*)value, (__nv_bfloat162*)ahi, (__nv_bfloat162*)alo, M_ * VD_ / 4);
    transconv_kernel<<<dim3(E_ / 32, VD_ / 32), 256>>>(Wv, whi, wlo, VD_, E_);
    hilo_gemm<128, false, 1><<<dim3(E_ / 128, M_ / 128, 1), 256, SMEM_P>>>(
        ahi, alo, whi, wlo, bv, nullptr, vhi, vlo,
        VD_, VD_, VD_, E_, 0, 0, 0, 0, 1, 1.0f);

    // ---- V transpose for AV B operand: [bh][s][d] -> [bh][d][s] ----
    transpose_hl_kernel<<<dim3(S_ / 32, D_ / 32, BH_), 256>>>(vhi, vlo, vthi, vtlo);

    // ---- scores: Wbuf[bh][i][j] = 0.125 * q.k ----
    hilo_gemm<128, false, 0><<<dim3(S_ / 128, S_ / 128, BH_), 256, SMEM_P>>>(
        qhi, qlo, khi, klo, nullptr, Wbuf, nullptr, nullptr,
        D_, D_, D_, S_,
        (long long)S_ * D_, (long long)S_ * D_,
        (long long)S_ * S_, 0, 1, 0.125f);

    // ---- softmax in-place ----
    softmax_kernel<<<(size_t)BH_ * S_, 256>>>(Wbuf);

    // ---- AV: writes bf16 hi/lo ctx directly as out-proj A operand ----
    hilo_gemm<64, true, 2><<<dim3(1, S_ / 128, BH_), 256, SMEM_A>>>(
        Wbuf, nullptr, vthi, vtlo, nullptr, nullptr, ahi, alo,
        S_, S_, S_, E_,
        (long long)S_ * S_, (long long)D_ * S_,
        0, 0, 16, 1.0f);

    // ---- output projection (fp32 out + bias) ----
    transconv_kernel<<<dim3(E_ / 32, E_ / 32), 256>>>(Wo, whi, wlo, E_, E_);
    hilo_gemm<128, false, 0><<<dim3(E_ / 128, M_ / 128, 1), 256, SMEM_P>>>(
        ahi, alo, whi, wlo, bo, out, nullptr, nullptr,
        E_, E_, E_, E_, 0, 0, 0, 0, 1, 1.0f);
}